// round 1
// baseline (speedup 1.0000x reference)
#include <cuda_runtime.h>
#include <cstdint>

#define BATCH 8
#define NN    2048
#define KDIM  256
#define DOUT  64
#define ALPHA 0.2f
#define ROWS_B 16

// ---- scratch (no allocations allowed) ----
__device__ float g_Wh[BATCH * NN * DOUT];   // 4 MB
__device__ float g_s1[BATCH * NN];
__device__ float g_s2[BATCH * NN];
__device__ float g_s2max[BATCH];

union F2U { unsigned long long u; float2 f; };

__device__ __forceinline__ void fma2(unsigned long long& c, unsigned long long a, unsigned long long b) {
    // c = a * b + c  (packed f32x2, full-rate FMA pipe on sm_103a)
    asm("fma.rn.f32x2 %0, %1, %2, %0;" : "+l"(c) : "l"(a), "l"(b));
}
__device__ __forceinline__ void add2(unsigned long long& c, unsigned long long a) {
    asm("add.rn.f32x2 %0, %0, %1;" : "+l"(c) : "l"(a));
}

// ============================================================
// Kernel A: Wh = h @ W  (+ s1 = Wh@a1, s2 = Wh@a2)
// block = 256 threads, 16 rows per block, K tiled by 64
// ============================================================
__global__ __launch_bounds__(256) void wh_kernel(const float* __restrict__ h,
                                                 const float* __restrict__ W,
                                                 const float* __restrict__ a) {
    __shared__ float Wt[64 * 64];     // 16 KB
    __shared__ float ht[16][64];      //  4 KB

    const int tid = threadIdx.x;
    const int r = tid >> 4;           // row-in-block 0..15
    const int q = tid & 15;           // dim-quad 0..15 (dims 4q..4q+3)
    const int gRow0 = blockIdx.x * 16;

    float acc0 = 0.f, acc1 = 0.f, acc2 = 0.f, acc3 = 0.f;

    for (int kt = 0; kt < 4; kt++) {
        // load W tile [64 k][64 d] (contiguous 16 KB) — coalesced float4
        const float4* Wg = reinterpret_cast<const float4*>(W + kt * 64 * 64);
        float4* Ws = reinterpret_cast<float4*>(Wt);
        #pragma unroll
        for (int it = 0; it < 4; it++) Ws[tid + it * 256] = Wg[tid + it * 256];
        // load h tile: 16 rows x 64 k
        *reinterpret_cast<float4*>(&ht[r][q * 4]) =
            *reinterpret_cast<const float4*>(h + (size_t)(gRow0 + r) * KDIM + kt * 64 + q * 4);
        __syncthreads();

        #pragma unroll 16
        for (int kk = 0; kk < 64; kk++) {
            const float hv = ht[r][kk];
            const float4 w = *reinterpret_cast<const float4*>(&Wt[kk * 64 + q * 4]);
            acc0 = fmaf(hv, w.x, acc0);
            acc1 = fmaf(hv, w.y, acc1);
            acc2 = fmaf(hv, w.z, acc2);
            acc3 = fmaf(hv, w.w, acc3);
        }
        __syncthreads();
    }

    const int gRow = gRow0 + r;
    *reinterpret_cast<float4*>(&g_Wh[(size_t)gRow * DOUT + q * 4]) =
        make_float4(acc0, acc1, acc2, acc3);

    // s1 = Wh . a[0:64], s2 = Wh . a[64:128]
    float s1 = acc0 * a[q * 4] + acc1 * a[q * 4 + 1] + acc2 * a[q * 4 + 2] + acc3 * a[q * 4 + 3];
    float s2 = acc0 * a[64 + q * 4] + acc1 * a[64 + q * 4 + 1] +
               acc2 * a[64 + q * 4 + 2] + acc3 * a[64 + q * 4 + 3];
    #pragma unroll
    for (int off = 8; off; off >>= 1) {
        s1 += __shfl_down_sync(0xffffffffu, s1, off, 16);
        s2 += __shfl_down_sync(0xffffffffu, s2, off, 16);
    }
    if (q == 0) { g_s1[gRow] = s1; g_s2[gRow] = s2; }
}

// ============================================================
// Kernel M: per-batch max of s2 (for the safe softmax bound)
// ============================================================
__global__ __launch_bounds__(256) void s2max_kernel() {
    __shared__ float red[8];
    const int b = blockIdx.x, tid = threadIdx.x;
    float m = -1e30f;
    for (int j = tid; j < NN; j += 256) m = fmaxf(m, g_s2[b * NN + j]);
    #pragma unroll
    for (int off = 16; off; off >>= 1) m = fmaxf(m, __shfl_down_sync(0xffffffffu, m, off));
    if ((tid & 31) == 0) red[tid >> 5] = m;
    __syncthreads();
    if (tid == 0) {
        float mm = red[0];
        #pragma unroll
        for (int w = 1; w < 8; w++) mm = fmaxf(mm, red[w]);
        g_s2max[b] = mm;
    }
}

// ============================================================
// Kernel B: one-pass masked softmax + P @ Wh, 16 rows / CTA
// thread layout in accumulate phase: q = tid&15 (dims 4q..4q+3),
// g = tid>>4 (j-subgroup). One Wh LDG.128 feeds 16 rows.
// ============================================================
__global__ __launch_bounds__(256, 2) void gat_main(const int* __restrict__ adj,
                                                   float* __restrict__ out) {
    __shared__ __align__(16) float2 p_sh[ROWS_B][256];   // 32 KB (aliased for reduction)
    __shared__ float m_sh[ROWS_B], s1_sh[ROWS_B];
    __shared__ float zwarp[8][ROWS_B];

    const int tid = threadIdx.x;
    const int gi0 = blockIdx.x * ROWS_B;     // global row base (covers b implicitly)
    const int b   = gi0 >> 11;               // /2048

    if (tid < ROWS_B) {
        const float s1 = g_s1[gi0 + tid];
        s1_sh[tid] = s1;
        const float t = s1 + g_s2max[b];
        m_sh[tid] = (t > 0.f) ? t : ALPHA * t;   // safe upper bound on e for this row
    }
    __syncthreads();

    unsigned long long acc[ROWS_B][2];
    float zacc[ROWS_B];
    #pragma unroll
    for (int r = 0; r < ROWS_B; r++) { acc[r][0] = 0ull; acc[r][1] = 0ull; zacc[r] = 0.f; }

    const int q = tid & 15;
    const int g = tid >> 4;

    for (int c = 0; c < NN / 256; c++) {
        const int jbase = c * 256;
        const int j = jbase + tid;
        const float s2j = g_s2[b * NN + j];
        const int* adjp = adj + (size_t)gi0 * NN + j;   // gi0*N == b*N*N + i_in_batch*N

        // ---- p phase: p = adj ? exp(lrelu(s1+s2) - m) : 0 ----
        #pragma unroll
        for (int r = 0; r < ROWS_B; r++) {
            const int av = adjp[(size_t)r * NN];
            const float t = s1_sh[r] + s2j;
            const float e = (t > 0.f) ? t : ALPHA * t;
            const float p = av ? __expf(e - m_sh[r]) : 0.f;
            zacc[r] += p;
            p_sh[r][tid] = make_float2(p, p);   // duplicated for f32x2 broadcast
        }
        __syncthreads();

        // ---- accumulate phase ----
        const float* whbase = g_Wh + (size_t)(b * NN + jbase) * DOUT + q * 4;
        #pragma unroll 4
        for (int it = 0; it < 16; it++) {
            const int jl = g + it * 16;
            const ulonglong2 wv =
                *reinterpret_cast<const ulonglong2*>(whbase + (size_t)jl * DOUT);
            #pragma unroll
            for (int r = 0; r < ROWS_B; r++) {
                const unsigned long long pv =
                    *reinterpret_cast<const unsigned long long*>(&p_sh[r][jl]);
                fma2(acc[r][0], wv.x, pv);
                fma2(acc[r][1], wv.y, pv);
            }
        }
        __syncthreads();
    }

    // ---- reduce: combine the two g-groups within each warp (lanes l and l+16 share q) ----
    #pragma unroll
    for (int r = 0; r < ROWS_B; r++) {
        #pragma unroll
        for (int k = 0; k < 2; k++) {
            const unsigned long long o = __shfl_down_sync(0xffffffffu, acc[r][k], 16);
            add2(acc[r][k], o);
        }
        float z = zacc[r];
        #pragma unroll
        for (int off = 16; off; off >>= 1) z += __shfl_down_sync(0xffffffffu, z, off);
        zacc[r] = z;
    }

    const int warp = tid >> 5, lane = tid & 31;
    if (lane == 0) {
        #pragma unroll
        for (int r = 0; r < ROWS_B; r++) zwarp[warp][r] = zacc[r];
    }

    // stage per-warp partials into (aliased) shared: part[8 warps][16 rows][16 q] float4
    float4 (*part)[ROWS_B][16] = reinterpret_cast<float4 (*)[ROWS_B][16]>(p_sh);
    if (lane < 16) {
        #pragma unroll
        for (int r = 0; r < ROWS_B; r++) {
            F2U u0; u0.u = acc[r][0];
            F2U u1; u1.u = acc[r][1];
            part[warp][r][lane] = make_float4(u0.f.x, u0.f.y, u1.f.x, u1.f.y);
        }
    }
    __syncthreads();

    // ---- final: each thread owns (row rr, quad qq) ----
    {
        const int rr = tid >> 4, qq = tid & 15;
        float4 s = part[0][rr][qq];
        #pragma unroll
        for (int w = 1; w < 8; w++) {
            const float4 t4 = part[w][rr][qq];
            s.x += t4.x; s.y += t4.y; s.z += t4.z; s.w += t4.w;
        }
        float Z = 0.f;
        #pragma unroll
        for (int w = 0; w < 8; w++) Z += zwarp[w][rr];
        const float inv = 1.f / Z;   // Z > 0 guaranteed: diagonal of adj is always 1
        s.x *= inv; s.y *= inv; s.z *= inv; s.w *= inv;
        *reinterpret_cast<float4*>(out + (size_t)(gi0 + rr) * DOUT + qq * 4) = s;
    }
}

// ============================================================
extern "C" void kernel_launch(void* const* d_in, const int* in_sizes, int n_in,
                              void* d_out, int out_size) {
    const float* h   = (const float*)d_in[0];
    const int*   adj = (const int*)d_in[1];
    const float* W   = (const float*)d_in[2];
    const float* a   = (const float*)d_in[3];
    float* out = (float*)d_out;

    wh_kernel<<<(BATCH * NN) / 16, 256>>>(h, W, a);
    s2max_kernel<<<BATCH, 256>>>();
    gat_main<<<(BATCH * NN) / ROWS_B, 256>>>(adj, out);
}

// round 3
// speedup vs baseline: 2.3082x; 2.3082x over previous
#include <cuda_runtime.h>
#include <cuda_bf16.h>
#include <cstdint>

#define BATCH 8
#define NN    2048
#define KDIM  256
#define DOUT  64
#define ALPHA 0.2f

// ---------------- scratch ----------------
__device__ __nv_bfloat16 g_WhT_h[BATCH * DOUT * NN];   // [b][d][j] 2MB
__device__ __nv_bfloat16 g_WhT_l[BATCH * DOUT * NN];   // 2MB
__device__ float g_s1[BATCH * NN];
__device__ float g_s2[BATCH * NN];
__device__ float g_s2max[BATCH];

// ---------------- helpers ----------------
__device__ __forceinline__ uint32_t smem_u32(const void* p) {
    uint32_t a;
    asm("{ .reg .u64 t; cvta.to.shared.u64 t, %1; cvt.u32.u64 %0, t; }" : "=r"(a) : "l"(p));
    return a;
}
__device__ __forceinline__ void ldsm4(uint32_t (&r)[4], uint32_t addr) {
    asm volatile("ldmatrix.sync.aligned.m8n8.x4.shared.b16 {%0,%1,%2,%3}, [%4];"
                 : "=r"(r[0]), "=r"(r[1]), "=r"(r[2]), "=r"(r[3]) : "r"(addr));
}
__device__ __forceinline__ void mma_bf16(float (&d)[4], const uint32_t (&a)[4],
                                         uint32_t b0, uint32_t b1) {
    asm volatile("mma.sync.aligned.m16n8k16.row.col.f32.bf16.bf16.f32 "
                 "{%0,%1,%2,%3}, {%4,%5,%6,%7}, {%8,%9}, {%0,%1,%2,%3};"
                 : "+f"(d[0]), "+f"(d[1]), "+f"(d[2]), "+f"(d[3])
                 : "r"(a[0]), "r"(a[1]), "r"(a[2]), "r"(a[3]), "r"(b0), "r"(b1));
}
__device__ __forceinline__ uint32_t pkbf2(float x, float y) {
    __nv_bfloat162 t = __floats2bfloat162_rn(x, y);
    return *reinterpret_cast<uint32_t*>(&t);
}

// ============================================================
// Kernel A: Wh = h @ W; emits s1, s2 and transposed bf16-split WhT.
// ============================================================
__global__ __launch_bounds__(256) void wh_kernel(const float* __restrict__ h,
                                                 const float* __restrict__ W,
                                                 const float* __restrict__ a) {
    __shared__ float4 ht4[32 * 16];
    __shared__ float4 wt4[32 * 16];
    __shared__ float ps1[16][64];
    __shared__ float ps2[16][64];
    __shared__ __align__(16) __nv_bfloat16 th[64][64];
    __shared__ __align__(16) __nv_bfloat16 tl[64][64];

    const int tid = threadIdx.x;
    const int grow0 = blockIdx.x * 64;
    const int b = grow0 >> 11;
    const int rowb = grow0 & 2047;
    const int rg = tid & 15;
    const int cg = tid >> 4;
    const int lrow = tid & 63, kq = tid >> 6;

    float a1v[4], a2v[4];
    #pragma unroll
    for (int c = 0; c < 4; c++) { a1v[c] = a[cg * 4 + c]; a2v[c] = a[64 + cg * 4 + c]; }

    float acc[4][4];
    #pragma unroll
    for (int r = 0; r < 4; r++)
        #pragma unroll
        for (int c = 0; c < 4; c++) acc[r][c] = 0.f;

    const float4* Wg4 = reinterpret_cast<const float4*>(W);

    for (int kt = 0; kt < 8; kt++) {
        const float4 hv0 = *reinterpret_cast<const float4*>(
            h + (size_t)(grow0 + lrow) * KDIM + kt * 32 + kq * 8);
        const float4 hv1 = *reinterpret_cast<const float4*>(
            h + (size_t)(grow0 + lrow) * KDIM + kt * 32 + kq * 8 + 4);
        const float4 wv0 = Wg4[kt * 512 + tid];
        const float4 wv1 = Wg4[kt * 512 + tid + 256];
        __syncthreads();
        float* htf = reinterpret_cast<float*>(ht4);
        htf[(kq * 8 + 0) * 64 + lrow] = hv0.x;
        htf[(kq * 8 + 1) * 64 + lrow] = hv0.y;
        htf[(kq * 8 + 2) * 64 + lrow] = hv0.z;
        htf[(kq * 8 + 3) * 64 + lrow] = hv0.w;
        htf[(kq * 8 + 4) * 64 + lrow] = hv1.x;
        htf[(kq * 8 + 5) * 64 + lrow] = hv1.y;
        htf[(kq * 8 + 6) * 64 + lrow] = hv1.z;
        htf[(kq * 8 + 7) * 64 + lrow] = hv1.w;
        wt4[tid] = wv0;
        wt4[tid + 256] = wv1;
        __syncthreads();

        #pragma unroll 8
        for (int k = 0; k < 32; k++) {
            const float4 av = ht4[k * 16 + rg];
            const float4 bv = wt4[k * 16 + cg];
            const float ar[4] = {av.x, av.y, av.z, av.w};
            const float br[4] = {bv.x, bv.y, bv.z, bv.w};
            #pragma unroll
            for (int r = 0; r < 4; r++)
                #pragma unroll
                for (int c = 0; c < 4; c++) acc[r][c] = fmaf(ar[r], br[c], acc[r][c]);
        }
    }
    __syncthreads();

    #pragma unroll
    for (int r = 0; r < 4; r++) {
        float p1 = 0.f, p2 = 0.f;
        #pragma unroll
        for (int c = 0; c < 4; c++) {
            const float x = acc[r][c];
            p1 = fmaf(x, a1v[c], p1);
            p2 = fmaf(x, a2v[c], p2);
            const __nv_bfloat16 hi = __float2bfloat16_rn(x);
            const __nv_bfloat16 lo = __float2bfloat16_rn(x - __bfloat162float(hi));
            th[cg * 4 + c][rg * 4 + r] = hi;
            tl[cg * 4 + c][rg * 4 + r] = lo;
        }
        ps1[cg][rg * 4 + r] = p1;
        ps2[cg][rg * 4 + r] = p2;
    }
    __syncthreads();

    if (tid < 64) {
        float s1 = 0.f, s2 = 0.f;
        #pragma unroll
        for (int g = 0; g < 16; g++) { s1 += ps1[g][tid]; s2 += ps2[g][tid]; }
        g_s1[grow0 + tid] = s1;
        g_s2[grow0 + tid] = s2;
    }

    #pragma unroll
    for (int c = 0; c < 4; c++) {
        const int idx = tid + 256 * c;
        const int spl = idx >> 9;
        const int id2 = idx & 511;
        const int d = id2 >> 3;
        const int c8 = id2 & 7;
        const uint4 val = *reinterpret_cast<const uint4*>((spl ? tl[d] : th[d]) + c8 * 8);
        __nv_bfloat16* dst = (spl ? g_WhT_l : g_WhT_h) +
                             ((size_t)b * DOUT + d) * NN + rowb + c8 * 8;
        *reinterpret_cast<uint4*>(dst) = val;
    }
}

// ============================================================
// Kernel M: per-batch max of s2
// ============================================================
__global__ __launch_bounds__(256) void s2max_kernel() {
    __shared__ float red[8];
    const int b = blockIdx.x, tid = threadIdx.x;
    float m = -1e30f;
    for (int j = tid; j < NN; j += 256) m = fmaxf(m, g_s2[b * NN + j]);
    #pragma unroll
    for (int off = 16; off; off >>= 1) m = fmaxf(m, __shfl_down_sync(0xffffffffu, m, off));
    if ((tid & 31) == 0) red[tid >> 5] = m;
    __syncthreads();
    if (tid == 0) {
        float mm = red[0];
        #pragma unroll
        for (int w = 1; w < 8; w++) mm = fmaxf(mm, red[w]);
        g_s2max[b] = mm;
    }
}

// ============================================================
// Kernel B: HMMA (mma.sync) GAT main. 128 CTAs x 128 rows, 8 warps,
// 16 rows/warp, K-chunks of 64 j. 3-MMA bf16 hi/lo split.
// ============================================================
#define OFF_PHI 0
#define OFF_PLO 16384
#define OFF_WHI 32768
#define OFF_WLO 40960
#define OFF_U   49152
#define OFF_V   57344
#define OFF_AS  65536
#define OFF_BS  66048
#define OFF_Z   66560
#define GAT_SMEM 67136

__global__ __launch_bounds__(256, 1) void gat_main(const int* __restrict__ adj,
                                                   float* __restrict__ out) {
    extern __shared__ char sm[];
    const uint32_t smb = smem_u32(sm);
    const int tid = threadIdx.x;
    const int wid = tid >> 5, lid = tid & 31;
    const int gi0 = blockIdx.x * 128;
    const int b = gi0 >> 11;

    float* u_sh = reinterpret_cast<float*>(sm + OFF_U);
    float* v_sh = reinterpret_cast<float*>(sm + OFF_V);
    float* As = reinterpret_cast<float*>(sm + OFF_AS);
    float* Bs = reinterpret_cast<float*>(sm + OFF_BS);
    float* zf = reinterpret_cast<float*>(sm + OFF_Z);

    // ---- prologue: u, v (per batch), A, B (per row) ----
    const float s2m = g_s2max[b];
    for (int j = tid; j < NN; j += 256) {
        const float s2 = g_s2[b * NN + j];
        u_sh[j] = __expf(s2);
        v_sh[j] = __expf(ALPHA * s2);
    }
    if (tid < 128) {
        const float s1 = g_s1[gi0 + tid];
        const float t = s1 + s2m;
        const float m = (t > 0.f) ? t : ALPHA * t;
        As[tid] = 0.5f * __expf(s1 - m);
        Bs[tid] = 0.5f * __expf(ALPHA * s1 - m);
    }
    __syncthreads();

    // ---- per-thread geometry ----
    const int prow = tid >> 4;            // P-build base row (0..15)
    const int chunk = tid & 15;           // 4-j chunk within 64
    const int chunk4 = chunk * 4;

    float Ar[8], Br[8];
    #pragma unroll
    for (int i = 0; i < 8; i++) { Ar[i] = As[prow + 16 * i]; Br[i] = Bs[prow + 16 * i]; }

    float acc[8][4];
    #pragma unroll
    for (int n = 0; n < 8; n++)
        #pragma unroll
        for (int k = 0; k < 4; k++) acc[n][k] = 0.f;
    float zacc[8];
    #pragma unroll
    for (int i = 0; i < 8; i++) zacc[i] = 0.f;

    // ldmatrix lane geometry
    const int rr = lid & 7, q = lid >> 3;
    const int qh = q >> 1, ql = q & 1;
    const int m0 = wid * 16;
    const int rowA = m0 + rr + (ql << 3);
    const uint32_t baseA = (uint32_t)(rowA * 128);
    const int xA = rowA & 7;
    const int rbB = (qh << 3) + rr;       // + ntp*16 -> B (d) row

    // W staging geometry
    const int wdrow = tid >> 3, wun = tid & 7;

    for (int jt = 0; jt < 32; jt++) {
        const int j0 = jt * 64;

        // ---- stage WhT tile [64 d][64 j] hi+lo into swizzled shared ----
        {
            const size_t s0 = ((size_t)(b * DOUT + wdrow)) * NN + j0 + wun * 8;
            const size_t s1 = s0 + (size_t)32 * NN;
            const uint32_t d0 = (uint32_t)(wdrow * 128 + ((wun ^ (wdrow & 7)) << 4));
            const uint32_t d1 = (uint32_t)((wdrow + 32) * 128 + ((wun ^ ((wdrow + 32) & 7)) << 4));
            *reinterpret_cast<uint4*>(sm + OFF_WHI + d0) = *reinterpret_cast<const uint4*>(g_WhT_h + s0);
            *reinterpret_cast<uint4*>(sm + OFF_WHI + d1) = *reinterpret_cast<const uint4*>(g_WhT_h + s1);
            *reinterpret_cast<uint4*>(sm + OFF_WLO + d0) = *reinterpret_cast<const uint4*>(g_WhT_l + s0);
            *reinterpret_cast<uint4*>(sm + OFF_WLO + d1) = *reinterpret_cast<const uint4*>(g_WhT_l + s1);
        }

        // ---- build P tile [128 rows][64 j] hi+lo ----
        const float4 uu = *reinterpret_cast<const float4*>(u_sh + j0 + chunk4);
        const float4 vv = *reinterpret_cast<const float4*>(v_sh + j0 + chunk4);
        #pragma unroll
        for (int i = 0; i < 8; i++) {
            const int row = prow + 16 * i;
            const int4 av = *reinterpret_cast<const int4*>(
                adj + (size_t)(gi0 + row) * NN + j0 + chunk4);
            float4 p;
            p.x = fmaxf(Ar[i] * uu.x, Br[i] * vv.x) * __int_as_float(av.x << 30);
            p.y = fmaxf(Ar[i] * uu.y, Br[i] * vv.y) * __int_as_float(av.y << 30);
            p.z = fmaxf(Ar[i] * uu.z, Br[i] * vv.z) * __int_as_float(av.z << 30);
            p.w = fmaxf(Ar[i] * uu.w, Br[i] * vv.w) * __int_as_float(av.w << 30);
            zacc[i] += (p.x + p.y) + (p.z + p.w);

            // hi = truncate-to-bf16 (lo captures remainder exactly)
            const uint32_t ux = __float_as_uint(p.x), uy = __float_as_uint(p.y);
            const uint32_t uz = __float_as_uint(p.z), uw = __float_as_uint(p.w);
            const uint32_t h0 = __byte_perm(ux, uy, 0x7632);
            const uint32_t h1 = __byte_perm(uz, uw, 0x7632);
            const uint32_t l0 = pkbf2(p.x - __uint_as_float(ux & 0xFFFF0000u),
                                      p.y - __uint_as_float(uy & 0xFFFF0000u));
            const uint32_t l1 = pkbf2(p.z - __uint_as_float(uz & 0xFFFF0000u),
                                      p.w - __uint_as_float(uw & 0xFFFF0000u));
            const uint32_t sw = (uint32_t)(row * 128 + (((chunk >> 1) ^ (row & 7)) << 4) +
                                           ((chunk & 1) << 3));
            *reinterpret_cast<uint2*>(sm + OFF_PHI + sw) = make_uint2(h0, h1);
            *reinterpret_cast<uint2*>(sm + OFF_PLO + sw) = make_uint2(l0, l1);
        }
        __syncthreads();

        // ---- HMMA phase ----
        #pragma unroll
        for (int t = 0; t < 4; t++) {
            uint32_t Ah[4], Al[4];
            const uint32_t ua = baseA + (uint32_t)((((2 * t + qh) ^ xA) << 4));
            ldsm4(Ah, smb + OFF_PHI + ua);
            ldsm4(Al, smb + OFF_PLO + ua);
            #pragma unroll
            for (int ntp = 0; ntp < 4; ntp++) {
                const int rowB = ntp * 16 + rbB;
                const uint32_t ab = (uint32_t)(rowB * 128 +
                                               (((2 * t + ql) ^ (rowB & 7)) << 4));
                uint32_t Bh[4], Bl[4];
                ldsm4(Bh, smb + OFF_WHI + ab);
                ldsm4(Bl, smb + OFF_WLO + ab);
                mma_bf16(acc[2 * ntp],     Ah, Bh[0], Bh[1]);
                mma_bf16(acc[2 * ntp],     Ah, Bl[0], Bl[1]);
                mma_bf16(acc[2 * ntp],     Al, Bh[0], Bh[1]);
                mma_bf16(acc[2 * ntp + 1], Ah, Bh[2], Bh[3]);
                mma_bf16(acc[2 * ntp + 1], Ah, Bl[2], Bl[3]);
                mma_bf16(acc[2 * ntp + 1], Al, Bh[2], Bh[3]);
            }
        }
        __syncthreads();
    }

    // ---- Z reduction (alias P_HI region) ----
    float* zp = reinterpret_cast<float*>(sm + OFF_PHI);
    #pragma unroll
    for (int i = 0; i < 8; i++) zp[i * 256 + tid] = zacc[i];
    __syncthreads();
    if (tid < 128) {
        const float* src = zp + (tid >> 4) * 256 + (tid & 15) * 16;
        float z = 0.f;
        #pragma unroll
        for (int t = 0; t < 16; t++) z += src[t];
        zf[tid] = z;
    }
    __syncthreads();

    // ---- normalize + store ----
    const int r0 = m0 + (lid >> 2), r1 = r0 + 8;
    const float inv0 = 1.f / zf[r0];
    const float inv1 = 1.f / zf[r1];
    float* o0 = out + (size_t)(gi0 + r0) * DOUT + (lid & 3) * 2;
    float* o1 = out + (size_t)(gi0 + r1) * DOUT + (lid & 3) * 2;
    #pragma unroll
    for (int nt = 0; nt < 8; nt++) {
        *reinterpret_cast<float2*>(o0 + nt * 8) = make_float2(acc[nt][0] * inv0, acc[nt][1] * inv0);
        *reinterpret_cast<float2*>(o1 + nt * 8) = make_float2(acc[nt][2] * inv1, acc[nt][3] * inv1);
    }
}

// ============================================================
extern "C" void kernel_launch(void* const* d_in, const int* in_sizes, int n_in,
                              void* d_out, int out_size) {
    const float* h   = (const float*)d_in[0];
    const int*   adj = (const int*)d_in[1];
    const float* W   = (const float*)d_in[2];
    const float* a   = (const float*)d_in[3];
    float* out = (float*)d_out;

    cudaFuncSetAttribute(gat_main, cudaFuncAttributeMaxDynamicSharedMemorySize, GAT_SMEM);

    wh_kernel<<<(BATCH * NN) / 64, 256>>>(h, W, a);
    s2max_kernel<<<BATCH, 256>>>();
    gat_main<<<(BATCH * NN) / 128, 256, GAT_SMEM>>>(adj, out);
}

// round 5
// speedup vs baseline: 3.1107x; 1.3477x over previous
#include <cuda_runtime.h>
#include <cuda_bf16.h>
#include <cstdint>

#define BATCH 8
#define NN    2048
#define KDIM  256
#define DOUT  64
#define ALPHA 0.2f

// ---------------- scratch ----------------
__device__ __nv_bfloat16 g_WhT_h[BATCH * DOUT * NN];   // [b][d][j] 2MB
__device__ __nv_bfloat16 g_WhT_l[BATCH * DOUT * NN];   // 2MB
__device__ float g_s1[BATCH * NN];
__device__ float g_s2[BATCH * NN];
__device__ float g_s2max[BATCH];

// ---------------- helpers ----------------
__device__ __forceinline__ uint32_t smem_u32(const void* p) {
    uint32_t a;
    asm("{ .reg .u64 t; cvta.to.shared.u64 t, %1; cvt.u32.u64 %0, t; }" : "=r"(a) : "l"(p));
    return a;
}
__device__ __forceinline__ void ldsm4(uint32_t (&r)[4], uint32_t addr) {
    asm volatile("ldmatrix.sync.aligned.m8n8.x4.shared.b16 {%0,%1,%2,%3}, [%4];"
                 : "=r"(r[0]), "=r"(r[1]), "=r"(r[2]), "=r"(r[3]) : "r"(addr));
}
__device__ __forceinline__ void mma_bf16(float (&d)[4], const uint32_t (&a)[4],
                                         uint32_t b0, uint32_t b1) {
    asm volatile("mma.sync.aligned.m16n8k16.row.col.f32.bf16.bf16.f32 "
                 "{%0,%1,%2,%3}, {%4,%5,%6,%7}, {%8,%9}, {%0,%1,%2,%3};"
                 : "+f"(d[0]), "+f"(d[1]), "+f"(d[2]), "+f"(d[3])
                 : "r"(a[0]), "r"(a[1]), "r"(a[2]), "r"(a[3]), "r"(b0), "r"(b1));
}
__device__ __forceinline__ uint32_t pkbf2(float x, float y) {
    __nv_bfloat162 t = __floats2bfloat162_rn(x, y);
    return *reinterpret_cast<uint32_t*>(&t);
}
__device__ __forceinline__ uint32_t hibits2(float x, float y) {
    return __byte_perm(__float_as_uint(x), __float_as_uint(y), 0x7632);
}
__device__ __forceinline__ float resid(float x) {
    return x - __uint_as_float(__float_as_uint(x) & 0xFFFF0000u);
}

// shared MMA inner phase: A [128 rows x 64k] hi/lo, B [64 rows x 64k] hi/lo,
// 3-split (Ah*Bh + Ah*Bl + Al*Bh), acc[8][4] fp32.
__device__ __forceinline__ void mma_phase(uint32_t smb,
    uint32_t offPhi, uint32_t offPlo, uint32_t offWhi, uint32_t offWlo,
    uint32_t baseA, int xA, int qh, int ql, int rbB, float (&acc)[8][4]) {
    #pragma unroll
    for (int t = 0; t < 4; t++) {
        uint32_t Ah[4], Al[4];
        const uint32_t ua = baseA + (uint32_t)((((2 * t + qh) ^ xA)) << 4);
        ldsm4(Ah, smb + offPhi + ua);
        ldsm4(Al, smb + offPlo + ua);
        #pragma unroll
        for (int ntp = 0; ntp < 4; ntp++) {
            const int rowB = ntp * 16 + rbB;
            const uint32_t ab = (uint32_t)(rowB * 128 + (((2 * t + ql) ^ (rowB & 7)) << 4));
            uint32_t Bh[4], Bl[4];
            ldsm4(Bh, smb + offWhi + ab);
            ldsm4(Bl, smb + offWlo + ab);
            mma_bf16(acc[2 * ntp],     Ah, Bh[0], Bh[1]);
            mma_bf16(acc[2 * ntp],     Ah, Bl[0], Bl[1]);
            mma_bf16(acc[2 * ntp],     Al, Bh[0], Bh[1]);
            mma_bf16(acc[2 * ntp + 1], Ah, Bh[2], Bh[3]);
            mma_bf16(acc[2 * ntp + 1], Ah, Bl[2], Bl[3]);
            mma_bf16(acc[2 * ntp + 1], Al, Bh[2], Bh[3]);
        }
    }
}

// ============================================================
// Kernel A (HMMA): Wh = h @ W; emits s1, s2 and WhT bf16-split.
// 128 CTAs x 128 rows, 8 warps, K chunks of 64.
// ============================================================
#define WOFF_HH 0
#define WOFF_HL 16384
#define WOFF_WH 32768
#define WOFF_WL 40960
#define WOFF_TRH 0
#define WOFF_TRL 16384
#define WH_SMEM 49152

__global__ __launch_bounds__(256, 1) void wh_kernel(const float* __restrict__ h,
                                                    const float* __restrict__ W,
                                                    const float* __restrict__ a) {
    extern __shared__ char sw[];
    const uint32_t smb = smem_u32(sw);
    const int tid = threadIdx.x;
    const int wid = tid >> 5, lid = tid & 31;
    const int gi0 = blockIdx.x * 128;
    const int b = gi0 >> 11;
    const int rowb = gi0 & 2047;

    float acc[8][4];
    #pragma unroll
    for (int n = 0; n < 8; n++)
        #pragma unroll
        for (int k = 0; k < 4; k++) acc[n][k] = 0.f;

    // ldsm geometry
    const int rr = lid & 7, q = lid >> 3, qh = q >> 1, ql = q & 1;
    const int m0 = wid * 16;
    const int rowA = m0 + rr + (ql << 3);
    const uint32_t baseA = (uint32_t)(rowA * 128);
    const int xA = rowA & 7;
    const int rbB = (qh << 3) + rr;

    // h staging: thread = (row, half of 32 k)
    const int hrow = tid >> 1, hhalf = tid & 1;
    const float* hsrc = h + (size_t)(gi0 + hrow) * KDIM + hhalf * 32;
    // W staging: thread = (d, 16-k group)
    const int wdd = tid >> 2, wkg = tid & 3;

    for (int kt = 0; kt < 4; kt++) {
        __syncthreads();
        // ---- stage h chunk [128 rows][64 k] hi/lo ----
        #pragma unroll
        for (int g = 0; g < 4; g++) {
            const float4 f0 = *reinterpret_cast<const float4*>(hsrc + kt * 64 + g * 8);
            const float4 f1 = *reinterpret_cast<const float4*>(hsrc + kt * 64 + g * 8 + 4);
            uint4 hi4, lo4;
            hi4.x = hibits2(f0.x, f0.y); hi4.y = hibits2(f0.z, f0.w);
            hi4.z = hibits2(f1.x, f1.y); hi4.w = hibits2(f1.z, f1.w);
            lo4.x = pkbf2(resid(f0.x), resid(f0.y));
            lo4.y = pkbf2(resid(f0.z), resid(f0.w));
            lo4.z = pkbf2(resid(f1.x), resid(f1.y));
            lo4.w = pkbf2(resid(f1.z), resid(f1.w));
            const int gran = hhalf * 4 + g;
            const uint32_t addr = (uint32_t)(hrow * 128 + ((gran ^ (hrow & 7)) << 4));
            *reinterpret_cast<uint4*>(sw + WOFF_HH + addr) = hi4;
            *reinterpret_cast<uint4*>(sw + WOFF_HL + addr) = lo4;
        }
        // ---- stage W^T chunk [64 d][64 k] hi/lo ----
        {
            uint32_t hi[8], lo[8];
            #pragma unroll
            for (int t = 0; t < 8; t++) {
                const float x0 = W[(kt * 64 + wkg * 16 + 2 * t) * DOUT + wdd];
                const float x1 = W[(kt * 64 + wkg * 16 + 2 * t + 1) * DOUT + wdd];
                hi[t] = hibits2(x0, x1);
                lo[t] = pkbf2(resid(x0), resid(x1));
            }
            const uint32_t a0 = (uint32_t)(wdd * 128 + (((wkg * 2) ^ (wdd & 7)) << 4));
            const uint32_t a1 = (uint32_t)(wdd * 128 + (((wkg * 2 + 1) ^ (wdd & 7)) << 4));
            *reinterpret_cast<uint4*>(sw + WOFF_WH + a0) = make_uint4(hi[0], hi[1], hi[2], hi[3]);
            *reinterpret_cast<uint4*>(sw + WOFF_WH + a1) = make_uint4(hi[4], hi[5], hi[6], hi[7]);
            *reinterpret_cast<uint4*>(sw + WOFF_WL + a0) = make_uint4(lo[0], lo[1], lo[2], lo[3]);
            *reinterpret_cast<uint4*>(sw + WOFF_WL + a1) = make_uint4(lo[4], lo[5], lo[6], lo[7]);
        }
        __syncthreads();
        mma_phase(smb, WOFF_HH, WOFF_HL, WOFF_WH, WOFF_WL, baseA, xA, qh, ql, rbB, acc);
    }
    __syncthreads();

    // ---- epilogue: s1/s2 + WhT split staging ----
    const int r0 = m0 + (lid >> 2), r1 = r0 + 8;
    float s1r0 = 0.f, s2r0 = 0.f, s1r1 = 0.f, s2r1 = 0.f;
    __nv_bfloat16* trh = reinterpret_cast<__nv_bfloat16*>(sw + WOFF_TRH);
    __nv_bfloat16* trl = reinterpret_cast<__nv_bfloat16*>(sw + WOFF_TRL);
    #pragma unroll
    for (int nt = 0; nt < 8; nt++) {
        const int d0 = nt * 8 + (lid & 3) * 2;
        const float a10 = a[d0], a11 = a[d0 + 1];
        const float a20 = a[64 + d0], a21 = a[64 + d0 + 1];
        s1r0 = fmaf(acc[nt][0], a10, fmaf(acc[nt][1], a11, s1r0));
        s2r0 = fmaf(acc[nt][0], a20, fmaf(acc[nt][1], a21, s2r0));
        s1r1 = fmaf(acc[nt][2], a10, fmaf(acc[nt][3], a11, s1r1));
        s2r1 = fmaf(acc[nt][2], a20, fmaf(acc[nt][3], a21, s2r1));
        #pragma unroll
        for (int e = 0; e < 2; e++) {
            const float x0 = acc[nt][e], x1 = acc[nt][2 + e];
            const __nv_bfloat16 h0 = __float2bfloat16_rn(x0);
            const __nv_bfloat16 h1 = __float2bfloat16_rn(x1);
            trh[(d0 + e) * 128 + r0] = h0;
            trh[(d0 + e) * 128 + r1] = h1;
            trl[(d0 + e) * 128 + r0] = __float2bfloat16_rn(x0 - __bfloat162float(h0));
            trl[(d0 + e) * 128 + r1] = __float2bfloat16_rn(x1 - __bfloat162float(h1));
        }
    }
    #pragma unroll
    for (int off = 1; off <= 2; off <<= 1) {
        s1r0 += __shfl_xor_sync(0xffffffffu, s1r0, off);
        s2r0 += __shfl_xor_sync(0xffffffffu, s2r0, off);
        s1r1 += __shfl_xor_sync(0xffffffffu, s1r1, off);
        s2r1 += __shfl_xor_sync(0xffffffffu, s2r1, off);
    }
    if ((lid & 3) == 0) {
        g_s1[gi0 + r0] = s1r0; g_s2[gi0 + r0] = s2r0;
        g_s1[gi0 + r1] = s1r1; g_s2[gi0 + r1] = s2r1;
    }
    __syncthreads();

    // ---- write WhT (coalesced): 2048 16B chunks = 2 splits x 64 d x 16 row-chunks ----
    #pragma unroll
    for (int c = 0; c < 8; c++) {
        const int idx = tid + 256 * c;          // 0..2047
        const int spl = idx >> 10;              // 0 = hi, 1 = lo
        const int d = (idx >> 4) & 63;          // dim 0..63
        const int c16 = idx & 15;               // row chunk 0..15 (8 rows each)
        const __nv_bfloat16* src = (spl ? trl : trh) + d * 128 + c16 * 8;
        const uint4 val = *reinterpret_cast<const uint4*>(src);
        __nv_bfloat16* dst = (spl ? g_WhT_l : g_WhT_h) +
                             ((size_t)(b * DOUT + d)) * NN + rowb + c16 * 8;
        *reinterpret_cast<uint4*>(dst) = val;
    }
}

// ============================================================
// Kernel M: per-batch max of s2
// ============================================================
__global__ __launch_bounds__(256) void s2max_kernel() {
    __shared__ float red[8];
    const int b = blockIdx.x, tid = threadIdx.x;
    float m = -1e30f;
    for (int j = tid; j < NN; j += 256) m = fmaxf(m, g_s2[b * NN + j]);
    #pragma unroll
    for (int off = 16; off; off >>= 1) m = fmaxf(m, __shfl_down_sync(0xffffffffu, m, off));
    if ((tid & 31) == 0) red[tid >> 5] = m;
    __syncthreads();
    if (tid == 0) {
        float mm = red[0];
        #pragma unroll
        for (int w = 1; w < 8; w++) mm = fmaxf(mm, red[w]);
        g_s2max[b] = mm;
    }
}

// ============================================================
// Kernel B: pipelined HMMA GAT main. 128 CTAs x 128 rows, 8 warps.
// 2-stage ping-pong: prefetch(jt+1) -> mma(jt) -> build(jt+1) -> bar.
// ============================================================
#define OFF_PHI(s) ((s) * 16384)
#define OFF_PLO(s) (32768 + (s) * 16384)
#define OFF_WHI(s) (65536 + (s) * 8192)
#define OFF_WLO(s) (81920 + (s) * 8192)
#define OFF_U   98304
#define OFF_V   106496
#define OFF_AS  114688
#define OFF_BS  115200
#define OFF_Z   115712
#define GAT_SMEM 116736

__global__ __launch_bounds__(256, 1) void gat_main(const int* __restrict__ adj,
                                                   float* __restrict__ out) {
    extern __shared__ char sm[];
    const uint32_t smb = smem_u32(sm);
    const int tid = threadIdx.x;
    const int wid = tid >> 5, lid = tid & 31;
    const int gi0 = blockIdx.x * 128;
    const int b = gi0 >> 11;

    float* u_sh = reinterpret_cast<float*>(sm + OFF_U);
    float* v_sh = reinterpret_cast<float*>(sm + OFF_V);
    float* As = reinterpret_cast<float*>(sm + OFF_AS);
    float* Bs = reinterpret_cast<float*>(sm + OFF_BS);
    float* zf = reinterpret_cast<float*>(sm + OFF_Z);

    // ---- prologue ----
    const float s2m = g_s2max[b];
    for (int j = tid; j < NN; j += 256) {
        const float s2 = g_s2[b * NN + j];
        u_sh[j] = __expf(s2);
        v_sh[j] = __expf(ALPHA * s2);
    }
    if (tid < 128) {
        const float s1 = g_s1[gi0 + tid];
        const float t = s1 + s2m;
        const float m = (t > 0.f) ? t : ALPHA * t;
        As[tid] = 0.5f * __expf(s1 - m);
        Bs[tid] = 0.5f * __expf(ALPHA * s1 - m);
    }
    __syncthreads();

    // ---- geometry ----
    const int prow = tid >> 4;
    const int chunk = tid & 15;
    const int chunk4 = chunk * 4;

    float Ar[8], Br[8];
    #pragma unroll
    for (int i = 0; i < 8; i++) { Ar[i] = As[prow + 16 * i]; Br[i] = Bs[prow + 16 * i]; }

    float acc[8][4];
    #pragma unroll
    for (int n = 0; n < 8; n++)
        #pragma unroll
        for (int k = 0; k < 4; k++) acc[n][k] = 0.f;
    float zacc[8];
    #pragma unroll
    for (int i = 0; i < 8; i++) zacc[i] = 0.f;

    const int rr = lid & 7, q = lid >> 3, qh = q >> 1, ql = q & 1;
    const int m0 = wid * 16;
    const int rowA = m0 + rr + (ql << 3);
    const uint32_t baseA = (uint32_t)(rowA * 128);
    const int xA = rowA & 7;
    const int rbB = (qh << 3) + rr;

    // W staging geometry (rows wdrow, wdrow+32)
    const int wdrow = tid >> 3, wun = tid & 7;
    const uint32_t wdst0 = (uint32_t)(wdrow * 128 + ((wun ^ (wdrow & 7)) << 4));
    const uint32_t wdst1 = (uint32_t)((wdrow + 32) * 128 + ((wun ^ ((wdrow + 32) & 7)) << 4));
    const __nv_bfloat16* wsh = g_WhT_h + ((size_t)(b * DOUT + wdrow)) * NN + wun * 8;
    const __nv_bfloat16* wsl = g_WhT_l + ((size_t)(b * DOUT + wdrow)) * NN + wun * 8;
    const int* asrc = adj + (size_t)(gi0 + prow) * NN + chunk4;

    // ---- prefetch registers ----
    int4 adjr[8];
    uint4 pwh0, pwh1, pwl0, pwl1;
    #pragma unroll
    for (int i = 0; i < 8; i++)
        adjr[i] = *reinterpret_cast<const int4*>(asrc + (size_t)(16 * i) * NN);
    pwh0 = *reinterpret_cast<const uint4*>(wsh);
    pwh1 = *reinterpret_cast<const uint4*>(wsh + (size_t)32 * NN);
    pwl0 = *reinterpret_cast<const uint4*>(wsl);
    pwl1 = *reinterpret_cast<const uint4*>(wsl + (size_t)32 * NN);

    // build stage 0 (j0 = 0)
    {
        *reinterpret_cast<uint4*>(sm + OFF_WHI(0) + wdst0) = pwh0;
        *reinterpret_cast<uint4*>(sm + OFF_WHI(0) + wdst1) = pwh1;
        *reinterpret_cast<uint4*>(sm + OFF_WLO(0) + wdst0) = pwl0;
        *reinterpret_cast<uint4*>(sm + OFF_WLO(0) + wdst1) = pwl1;
        const float4 uu = *reinterpret_cast<const float4*>(u_sh + chunk4);
        const float4 vv = *reinterpret_cast<const float4*>(v_sh + chunk4);
        #pragma unroll
        for (int i = 0; i < 8; i++) {
            const int row = prow + 16 * i;
            const int4 av = adjr[i];
            float4 p;
            p.x = fmaxf(Ar[i] * uu.x, Br[i] * vv.x) * __int_as_float(av.x << 30);
            p.y = fmaxf(Ar[i] * uu.y, Br[i] * vv.y) * __int_as_float(av.y << 30);
            p.z = fmaxf(Ar[i] * uu.z, Br[i] * vv.z) * __int_as_float(av.z << 30);
            p.w = fmaxf(Ar[i] * uu.w, Br[i] * vv.w) * __int_as_float(av.w << 30);
            zacc[i] += (p.x + p.y) + (p.z + p.w);
            const uint32_t h0 = hibits2(p.x, p.y), h1 = hibits2(p.z, p.w);
            const uint32_t l0 = pkbf2(resid(p.x), resid(p.y));
            const uint32_t l1 = pkbf2(resid(p.z), resid(p.w));
            const uint32_t swo = (uint32_t)(row * 128 + (((chunk >> 1) ^ (row & 7)) << 4) +
                                            ((chunk & 1) << 3));
            *reinterpret_cast<uint2*>(sm + OFF_PHI(0) + swo) = make_uint2(h0, h1);
            *reinterpret_cast<uint2*>(sm + OFF_PLO(0) + swo) = make_uint2(l0, l1);
        }
    }
    __syncthreads();

    for (int jt = 0; jt < 32; jt++) {
        const int cur = jt & 1;
        const bool more = (jt < 31);
        const int jn = (jt + 1) * 64;

        // ---- prefetch next tile (regs) ----
        if (more) {
            #pragma unroll
            for (int i = 0; i < 8; i++)
                adjr[i] = *reinterpret_cast<const int4*>(asrc + (size_t)(16 * i) * NN + jn);
            pwh0 = *reinterpret_cast<const uint4*>(wsh + jn);
            pwh1 = *reinterpret_cast<const uint4*>(wsh + (size_t)32 * NN + jn);
            pwl0 = *reinterpret_cast<const uint4*>(wsl + jn);
            pwl1 = *reinterpret_cast<const uint4*>(wsl + (size_t)32 * NN + jn);
        }

        // ---- MMA on current stage ----
        if (cur == 0)
            mma_phase(smb, OFF_PHI(0), OFF_PLO(0), OFF_WHI(0), OFF_WLO(0),
                      baseA, xA, qh, ql, rbB, acc);
        else
            mma_phase(smb, OFF_PHI(1), OFF_PLO(1), OFF_WHI(1), OFF_WLO(1),
                      baseA, xA, qh, ql, rbB, acc);

        // ---- build next stage ----
        if (more) {
            const int nxt = cur ^ 1;
            *reinterpret_cast<uint4*>(sm + OFF_WHI(nxt) + wdst0) = pwh0;
            *reinterpret_cast<uint4*>(sm + OFF_WHI(nxt) + wdst1) = pwh1;
            *reinterpret_cast<uint4*>(sm + OFF_WLO(nxt) + wdst0) = pwl0;
            *reinterpret_cast<uint4*>(sm + OFF_WLO(nxt) + wdst1) = pwl1;
            const float4 uu = *reinterpret_cast<const float4*>(u_sh + jn + chunk4);
            const float4 vv = *reinterpret_cast<const float4*>(v_sh + jn + chunk4);
            #pragma unroll
            for (int i = 0; i < 8; i++) {
                const int row = prow + 16 * i;
                const int4 av = adjr[i];
                float4 p;
                p.x = fmaxf(Ar[i] * uu.x, Br[i] * vv.x) * __int_as_float(av.x << 30);
                p.y = fmaxf(Ar[i] * uu.y, Br[i] * vv.y) * __int_as_float(av.y << 30);
                p.z = fmaxf(Ar[i] * uu.z, Br[i] * vv.z) * __int_as_float(av.z << 30);
                p.w = fmaxf(Ar[i] * uu.w, Br[i] * vv.w) * __int_as_float(av.w << 30);
                zacc[i] += (p.x + p.y) + (p.z + p.w);
                const uint32_t h0 = hibits2(p.x, p.y), h1 = hibits2(p.z, p.w);
                const uint32_t l0 = pkbf2(resid(p.x), resid(p.y));
                const uint32_t l1 = pkbf2(resid(p.z), resid(p.w));
                const uint32_t swo = (uint32_t)(row * 128 + (((chunk >> 1) ^ (row & 7)) << 4) +
                                                ((chunk & 1) << 3));
                *reinterpret_cast<uint2*>(sm + OFF_PHI(nxt) + swo) = make_uint2(h0, h1);
                *reinterpret_cast<uint2*>(sm + OFF_PLO(nxt) + swo) = make_uint2(l0, l1);
            }
        }
        __syncthreads();
    }

    // ---- Z reduction (alias P region of stage 0) ----
    float* zp = reinterpret_cast<float*>(sm + OFF_PHI(0));
    #pragma unroll
    for (int i = 0; i < 8; i++) zp[i * 256 + tid] = zacc[i];
    __syncthreads();
    if (tid < 128) {
        const float* src = zp + (tid >> 4) * 256 + (tid & 15) * 16;
        float z = 0.f;
        #pragma unroll
        for (int t = 0; t < 16; t++) z += src[t];
        zf[tid] = z;
    }
    __syncthreads();

    // ---- normalize + store ----
    const int r0 = m0 + (lid >> 2), r1 = r0 + 8;
    const float inv0 = 1.f / zf[r0];
    const float inv1 = 1.f / zf[r1];
    float* o0 = out + (size_t)(gi0 + r0) * DOUT + (lid & 3) * 2;
    float* o1 = out + (size_t)(gi0 + r1) * DOUT + (lid & 3) * 2;
    #pragma unroll
    for (int nt = 0; nt < 8; nt++) {
        *reinterpret_cast<float2*>(o0 + nt * 8) = make_float2(acc[nt][0] * inv0, acc[nt][1] * inv0);
        *reinterpret_cast<float2*>(o1 + nt * 8) = make_float2(acc[nt][2] * inv1, acc[nt][3] * inv1);
    }
}

// ============================================================
extern "C" void kernel_launch(void* const* d_in, const int* in_sizes, int n_in,
                              void* d_out, int out_size) {
    const float* h   = (const float*)d_in[0];
    const int*   adj = (const int*)d_in[1];
    const float* W   = (const float*)d_in[2];
    const float* a   = (const float*)d_in[3];
    float* out = (float*)d_out;

    cudaFuncSetAttribute(gat_main, cudaFuncAttributeMaxDynamicSharedMemorySize, GAT_SMEM);
    cudaFuncSetAttribute(wh_kernel, cudaFuncAttributeMaxDynamicSharedMemorySize, WH_SMEM);

    wh_kernel<<<(BATCH * NN) / 128, 256, WH_SMEM>>>(h, W, a);
    s2max_kernel<<<BATCH, 256>>>();
    gat_main<<<(BATCH * NN) / 128, 256, GAT_SMEM>>>(adj, out);
}

// round 6
// speedup vs baseline: 3.6568x; 1.1756x over previous
#include <cuda_runtime.h>
#include <cuda_bf16.h>
#include <cuda_fp16.h>
#include <cstdint>

#define BATCH 8
#define NN    2048
#define KDIM  256
#define DOUT  64
#define ALPHA 0.2f

// ---------------- scratch ----------------
__device__ __half g_WhT[BATCH * DOUT * NN];   // [b][d][j] fp16, 2MB
__device__ float g_s1[BATCH * NN];
__device__ float g_s2[BATCH * NN];
__device__ float g_s2max[BATCH];

// ---------------- helpers ----------------
__device__ __forceinline__ uint32_t smem_u32(const void* p) {
    uint32_t a;
    asm("{ .reg .u64 t; cvta.to.shared.u64 t, %1; cvt.u32.u64 %0, t; }" : "=r"(a) : "l"(p));
    return a;
}
__device__ __forceinline__ void ldsm4(uint32_t (&r)[4], uint32_t addr) {
    asm volatile("ldmatrix.sync.aligned.m8n8.x4.shared.b16 {%0,%1,%2,%3}, [%4];"
                 : "=r"(r[0]), "=r"(r[1]), "=r"(r[2]), "=r"(r[3]) : "r"(addr));
}
__device__ __forceinline__ void mma_bf16(float (&d)[4], const uint32_t (&a)[4],
                                         uint32_t b0, uint32_t b1) {
    asm volatile("mma.sync.aligned.m16n8k16.row.col.f32.bf16.bf16.f32 "
                 "{%0,%1,%2,%3}, {%4,%5,%6,%7}, {%8,%9}, {%0,%1,%2,%3};"
                 : "+f"(d[0]), "+f"(d[1]), "+f"(d[2]), "+f"(d[3])
                 : "r"(a[0]), "r"(a[1]), "r"(a[2]), "r"(a[3]), "r"(b0), "r"(b1));
}
__device__ __forceinline__ void mma_f16(float (&d)[4], const uint32_t (&a)[4],
                                        uint32_t b0, uint32_t b1) {
    asm volatile("mma.sync.aligned.m16n8k16.row.col.f32.f16.f16.f32 "
                 "{%0,%1,%2,%3}, {%4,%5,%6,%7}, {%8,%9}, {%0,%1,%2,%3};"
                 : "+f"(d[0]), "+f"(d[1]), "+f"(d[2]), "+f"(d[3])
                 : "r"(a[0]), "r"(a[1]), "r"(a[2]), "r"(a[3]), "r"(b0), "r"(b1));
}
__device__ __forceinline__ uint32_t pkbf2(float x, float y) {
    __nv_bfloat162 t = __floats2bfloat162_rn(x, y);
    return *reinterpret_cast<uint32_t*>(&t);
}
__device__ __forceinline__ uint32_t hibits2(float x, float y) {
    return __byte_perm(__float_as_uint(x), __float_as_uint(y), 0x7632);
}
__device__ __forceinline__ float resid(float x) {
    return x - __uint_as_float(__float_as_uint(x) & 0xFFFF0000u);
}
__device__ __forceinline__ uint32_t pkhf2(float x, float y) {
    __half2 t = __floats2half2_rn(x, y);
    return *reinterpret_cast<uint32_t*>(&t);
}
__device__ __forceinline__ float2 uph2(uint32_t u) {
    __half2 t = *reinterpret_cast<__half2*>(&u);
    return __half22float2(t);
}

// ============================================================
// Kernel A (HMMA, unchanged structure): Wh = h @ W; emits s1, s2,
// and WhT as SINGLE fp16 (RN). 128 CTAs x 128 rows, 8 warps.
// ============================================================
#define WOFF_HH 0
#define WOFF_HL 16384
#define WOFF_WH 32768
#define WOFF_WL 40960
#define WOFF_TR 0
#define WH_SMEM 49152

__global__ __launch_bounds__(256, 1) void wh_kernel(const float* __restrict__ h,
                                                    const float* __restrict__ W,
                                                    const float* __restrict__ a) {
    extern __shared__ char sw[];
    const uint32_t smb = smem_u32(sw);
    const int tid = threadIdx.x;
    const int wid = tid >> 5, lid = tid & 31;
    const int gi0 = blockIdx.x * 128;
    const int b = gi0 >> 11;
    const int rowb = gi0 & 2047;

    float acc[8][4];
    #pragma unroll
    for (int n = 0; n < 8; n++)
        #pragma unroll
        for (int k = 0; k < 4; k++) acc[n][k] = 0.f;

    const int rr = lid & 7, q = lid >> 3, qh = q >> 1, ql = q & 1;
    const int m0 = wid * 16;
    const int rowA = m0 + rr + (ql << 3);
    const uint32_t baseA = (uint32_t)(rowA * 128);
    const int xA = rowA & 7;
    const int rbB = (qh << 3) + rr;

    const int hrow = tid >> 1, hhalf = tid & 1;
    const float* hsrc = h + (size_t)(gi0 + hrow) * KDIM + hhalf * 32;
    const int wdd = tid >> 2, wkg = tid & 3;

    for (int kt = 0; kt < 4; kt++) {
        __syncthreads();
        #pragma unroll
        for (int g = 0; g < 4; g++) {
            const float4 f0 = *reinterpret_cast<const float4*>(hsrc + kt * 64 + g * 8);
            const float4 f1 = *reinterpret_cast<const float4*>(hsrc + kt * 64 + g * 8 + 4);
            uint4 hi4, lo4;
            hi4.x = hibits2(f0.x, f0.y); hi4.y = hibits2(f0.z, f0.w);
            hi4.z = hibits2(f1.x, f1.y); hi4.w = hibits2(f1.z, f1.w);
            lo4.x = pkbf2(resid(f0.x), resid(f0.y));
            lo4.y = pkbf2(resid(f0.z), resid(f0.w));
            lo4.z = pkbf2(resid(f1.x), resid(f1.y));
            lo4.w = pkbf2(resid(f1.z), resid(f1.w));
            const int gran = hhalf * 4 + g;
            const uint32_t addr = (uint32_t)(hrow * 128 + ((gran ^ (hrow & 7)) << 4));
            *reinterpret_cast<uint4*>(sw + WOFF_HH + addr) = hi4;
            *reinterpret_cast<uint4*>(sw + WOFF_HL + addr) = lo4;
        }
        {
            uint32_t hi[8], lo[8];
            #pragma unroll
            for (int t = 0; t < 8; t++) {
                const float x0 = W[(kt * 64 + wkg * 16 + 2 * t) * DOUT + wdd];
                const float x1 = W[(kt * 64 + wkg * 16 + 2 * t + 1) * DOUT + wdd];
                hi[t] = hibits2(x0, x1);
                lo[t] = pkbf2(resid(x0), resid(x1));
            }
            const uint32_t a0 = (uint32_t)(wdd * 128 + (((wkg * 2) ^ (wdd & 7)) << 4));
            const uint32_t a1 = (uint32_t)(wdd * 128 + (((wkg * 2 + 1) ^ (wdd & 7)) << 4));
            *reinterpret_cast<uint4*>(sw + WOFF_WH + a0) = make_uint4(hi[0], hi[1], hi[2], hi[3]);
            *reinterpret_cast<uint4*>(sw + WOFF_WH + a1) = make_uint4(hi[4], hi[5], hi[6], hi[7]);
            *reinterpret_cast<uint4*>(sw + WOFF_WL + a0) = make_uint4(lo[0], lo[1], lo[2], lo[3]);
            *reinterpret_cast<uint4*>(sw + WOFF_WL + a1) = make_uint4(lo[4], lo[5], lo[6], lo[7]);
        }
        __syncthreads();
        // 3-split bf16 MMA
        #pragma unroll
        for (int t = 0; t < 4; t++) {
            uint32_t Ah[4], Al[4];
            const uint32_t ua = baseA + (uint32_t)(((2 * t + qh) ^ xA) << 4);
            ldsm4(Ah, smb + WOFF_HH + ua);
            ldsm4(Al, smb + WOFF_HL + ua);
            #pragma unroll
            for (int ntp = 0; ntp < 4; ntp++) {
                const int rowB = ntp * 16 + rbB;
                const uint32_t ab = (uint32_t)(rowB * 128 + (((2 * t + ql) ^ (rowB & 7)) << 4));
                uint32_t Bh[4], Bl[4];
                ldsm4(Bh, smb + WOFF_WH + ab);
                ldsm4(Bl, smb + WOFF_WL + ab);
                mma_bf16(acc[2 * ntp],     Ah, Bh[0], Bh[1]);
                mma_bf16(acc[2 * ntp],     Ah, Bl[0], Bl[1]);
                mma_bf16(acc[2 * ntp],     Al, Bh[0], Bh[1]);
                mma_bf16(acc[2 * ntp + 1], Ah, Bh[2], Bh[3]);
                mma_bf16(acc[2 * ntp + 1], Ah, Bl[2], Bl[3]);
                mma_bf16(acc[2 * ntp + 1], Al, Bh[2], Bh[3]);
            }
        }
    }
    __syncthreads();

    // ---- epilogue: s1/s2 + fp16 WhT staging ----
    const int r0 = m0 + (lid >> 2), r1 = r0 + 8;
    float s1r0 = 0.f, s2r0 = 0.f, s1r1 = 0.f, s2r1 = 0.f;
    __half* tr = reinterpret_cast<__half*>(sw + WOFF_TR);   // [64 d][128 r]
    #pragma unroll
    for (int nt = 0; nt < 8; nt++) {
        const int d0 = nt * 8 + (lid & 3) * 2;
        const float a10 = a[d0], a11 = a[d0 + 1];
        const float a20 = a[64 + d0], a21 = a[64 + d0 + 1];
        s1r0 = fmaf(acc[nt][0], a10, fmaf(acc[nt][1], a11, s1r0));
        s2r0 = fmaf(acc[nt][0], a20, fmaf(acc[nt][1], a21, s2r0));
        s1r1 = fmaf(acc[nt][2], a10, fmaf(acc[nt][3], a11, s1r1));
        s2r1 = fmaf(acc[nt][2], a20, fmaf(acc[nt][3], a21, s2r1));
        #pragma unroll
        for (int e = 0; e < 2; e++) {
            tr[(d0 + e) * 128 + r0] = __float2half_rn(acc[nt][e]);
            tr[(d0 + e) * 128 + r1] = __float2half_rn(acc[nt][2 + e]);
        }
    }
    #pragma unroll
    for (int off = 1; off <= 2; off <<= 1) {
        s1r0 += __shfl_xor_sync(0xffffffffu, s1r0, off);
        s2r0 += __shfl_xor_sync(0xffffffffu, s2r0, off);
        s1r1 += __shfl_xor_sync(0xffffffffu, s1r1, off);
        s2r1 += __shfl_xor_sync(0xffffffffu, s2r1, off);
    }
    if ((lid & 3) == 0) {
        g_s1[gi0 + r0] = s1r0; g_s2[gi0 + r0] = s2r0;
        g_s1[gi0 + r1] = s1r1; g_s2[gi0 + r1] = s2r1;
    }
    __syncthreads();

    // 1024 16B chunks = 64 d x 16 row-chunks
    #pragma unroll
    for (int c = 0; c < 4; c++) {
        const int idx = tid + 256 * c;
        const int d = idx >> 4;
        const int c16 = idx & 15;
        const uint4 val = *reinterpret_cast<const uint4*>(tr + d * 128 + c16 * 8);
        *reinterpret_cast<uint4*>(g_WhT + ((size_t)(b * DOUT + d)) * NN + rowb + c16 * 8) = val;
    }
}

// ============================================================
// Kernel M: per-batch max of s2
// ============================================================
__global__ __launch_bounds__(256) void s2max_kernel() {
    __shared__ float red[8];
    const int b = blockIdx.x, tid = threadIdx.x;
    float m = -1e30f;
    for (int j = tid; j < NN; j += 256) m = fmaxf(m, g_s2[b * NN + j]);
    #pragma unroll
    for (int off = 16; off; off >>= 1) m = fmaxf(m, __shfl_down_sync(0xffffffffu, m, off));
    if ((tid & 31) == 0) red[tid >> 5] = m;
    __syncthreads();
    if (tid == 0) {
        float mm = red[0];
        #pragma unroll
        for (int w = 1; w < 8; w++) mm = fmaxf(mm, red[w]);
        g_s2max[b] = mm;
    }
}

// ============================================================
// Kernel B: fp16 HMMA GAT main. 256 CTAs x 64 rows, 8 warps
// (warp = 16 rows x 32 dims), 2 CTAs/SM, 2 MMAs (P hi/lo x W fp16).
// 2-stage ping-pong: prefetch(jt+1) -> mma(jt) -> build(jt+1) -> bar.
// ============================================================
#define GOFF_PHI(s) ((s) * 8192)
#define GOFF_PLO(s) (16384 + (s) * 8192)
#define GOFF_WHI(s) (32768 + (s) * 8192)
#define GOFF_U   49152
#define GOFF_V   57344
#define GOFF_AS  65536
#define GOFF_BS  65792
#define GOFF_ZF  66048
#define GAT_SMEM 66560

__global__ __launch_bounds__(256, 2) void gat_main(const int* __restrict__ adj,
                                                   float* __restrict__ out) {
    extern __shared__ char sm[];
    const uint32_t smb = smem_u32(sm);
    const int tid = threadIdx.x;
    const int wid = tid >> 5, lid = tid & 31;
    const int gi0 = blockIdx.x * 64;
    const int b = gi0 >> 11;

    float* u_sh = reinterpret_cast<float*>(sm + GOFF_U);
    float* v_sh = reinterpret_cast<float*>(sm + GOFF_V);
    float* As = reinterpret_cast<float*>(sm + GOFF_AS);
    float* Bs = reinterpret_cast<float*>(sm + GOFF_BS);
    float* zf = reinterpret_cast<float*>(sm + GOFF_ZF);

    // ---- prologue ----
    const float s2m = g_s2max[b];
    for (int j = tid; j < NN; j += 256) {
        const float s2 = g_s2[b * NN + j];
        u_sh[j] = __expf(s2);
        v_sh[j] = __expf(ALPHA * s2);
    }
    if (tid < 64) {
        const float s1 = g_s1[gi0 + tid];
        const float t = s1 + s2m;
        const float m = (t > 0.f) ? t : ALPHA * t;
        As[tid] = 0.5f * __expf(s1 - m);
        Bs[tid] = 0.5f * __expf(ALPHA * s1 - m);
    }
    __syncthreads();

    // ---- geometry ----
    const int r16 = tid >> 4;          // build rows r16 + 16*i, i<4
    const int chunk = tid & 15;
    const int chunk4 = chunk * 4;

    float Ar[4], Br[4];
    #pragma unroll
    for (int i = 0; i < 4; i++) { Ar[i] = As[r16 + 16 * i]; Br[i] = Bs[r16 + 16 * i]; }

    float acc[4][4];
    #pragma unroll
    for (int n = 0; n < 4; n++)
        #pragma unroll
        for (int k = 0; k < 4; k++) acc[n][k] = 0.f;
    float zacc[4] = {0.f, 0.f, 0.f, 0.f};

    const int mq = wid & 3, nh = wid >> 2;     // warp: rows mq*16.., dims nh*32..
    const int rr = lid & 7, q = lid >> 3, qh = q >> 1, ql = q & 1;
    const int rowA = mq * 16 + rr + (ql << 3);
    const uint32_t baseA = (uint32_t)(rowA * 128);
    const int xA = rowA & 7;
    const int rbB = nh * 32 + (qh << 3) + rr;  // + ntp*16

    // W staging geometry (rows wdrow, wdrow+32)
    const int wdrow = tid >> 3, wun = tid & 7;
    const uint32_t wdst0 = (uint32_t)(wdrow * 128 + ((wun ^ (wdrow & 7)) << 4));
    const uint32_t wdst1 = (uint32_t)((wdrow + 32) * 128 + ((wun ^ ((wdrow + 32) & 7)) << 4));
    const __half* wsrc = g_WhT + ((size_t)(b * DOUT + wdrow)) * NN + wun * 8;
    const int* asrc = adj + (size_t)(gi0 + r16) * NN + chunk4;

    // ---- prefetch ----
    int4 adjr[4];
    uint4 pwh0, pwh1;
    #pragma unroll
    for (int i = 0; i < 4; i++)
        adjr[i] = *reinterpret_cast<const int4*>(asrc + (size_t)(16 * i) * NN);
    pwh0 = *reinterpret_cast<const uint4*>(wsrc);
    pwh1 = *reinterpret_cast<const uint4*>(wsrc + (size_t)32 * NN);

    // build stage 0
    {
        *reinterpret_cast<uint4*>(sm + GOFF_WHI(0) + wdst0) = pwh0;
        *reinterpret_cast<uint4*>(sm + GOFF_WHI(0) + wdst1) = pwh1;
        const float4 uu = *reinterpret_cast<const float4*>(u_sh + chunk4);
        const float4 vv = *reinterpret_cast<const float4*>(v_sh + chunk4);
        #pragma unroll
        for (int i = 0; i < 4; i++) {
            const int row = r16 + 16 * i;
            const int4 av = adjr[i];
            float4 p;
            p.x = fmaxf(Ar[i] * uu.x, Br[i] * vv.x) * __int_as_float(av.x << 30);
            p.y = fmaxf(Ar[i] * uu.y, Br[i] * vv.y) * __int_as_float(av.y << 30);
            p.z = fmaxf(Ar[i] * uu.z, Br[i] * vv.z) * __int_as_float(av.z << 30);
            p.w = fmaxf(Ar[i] * uu.w, Br[i] * vv.w) * __int_as_float(av.w << 30);
            zacc[i] += (p.x + p.y) + (p.z + p.w);
            const uint32_t h0 = pkhf2(p.x, p.y);
            const uint32_t h1 = pkhf2(p.z, p.w);
            const float2 f0 = uph2(h0), f1 = uph2(h1);
            const uint32_t l0 = pkhf2(p.x - f0.x, p.y - f0.y);
            const uint32_t l1 = pkhf2(p.z - f1.x, p.w - f1.y);
            const uint32_t swo = (uint32_t)(row * 128 + (((chunk >> 1) ^ (row & 7)) << 4) +
                                            ((chunk & 1) << 3));
            *reinterpret_cast<uint2*>(sm + GOFF_PHI(0) + swo) = make_uint2(h0, h1);
            *reinterpret_cast<uint2*>(sm + GOFF_PLO(0) + swo) = make_uint2(l0, l1);
        }
    }
    __syncthreads();

    for (int jt = 0; jt < 32; jt++) {
        const int cur = jt & 1;
        const bool more = (jt < 31);
        const int jn = (jt + 1) * 64;

        if (more) {
            #pragma unroll
            for (int i = 0; i < 4; i++)
                adjr[i] = *reinterpret_cast<const int4*>(asrc + (size_t)(16 * i) * NN + jn);
            pwh0 = *reinterpret_cast<const uint4*>(wsrc + jn);
            pwh1 = *reinterpret_cast<const uint4*>(wsrc + (size_t)32 * NN + jn);
        }

        // ---- MMA on current stage: 2 MMAs (Ph + Pl) x Wh ----
        {
            const uint32_t oPhi = GOFF_PHI(cur), oPlo = GOFF_PLO(cur), oWhi = GOFF_WHI(cur);
            #pragma unroll
            for (int t = 0; t < 4; t++) {
                uint32_t Ah[4], Al[4];
                const uint32_t ua = baseA + (uint32_t)(((2 * t + qh) ^ xA) << 4);
                ldsm4(Ah, smb + oPhi + ua);
                ldsm4(Al, smb + oPlo + ua);
                #pragma unroll
                for (int ntp = 0; ntp < 2; ntp++) {
                    const int rowB = ntp * 16 + rbB;
                    const uint32_t ab = (uint32_t)(rowB * 128 +
                                                   (((2 * t + ql) ^ (rowB & 7)) << 4));
                    uint32_t Bh[4];
                    ldsm4(Bh, smb + oWhi + ab);
                    mma_f16(acc[2 * ntp],     Ah, Bh[0], Bh[1]);
                    mma_f16(acc[2 * ntp],     Al, Bh[0], Bh[1]);
                    mma_f16(acc[2 * ntp + 1], Ah, Bh[2], Bh[3]);
                    mma_f16(acc[2 * ntp + 1], Al, Bh[2], Bh[3]);
                }
            }
        }

        // ---- build next stage ----
        if (more) {
            const int nxt = cur ^ 1;
            *reinterpret_cast<uint4*>(sm + GOFF_WHI(nxt) + wdst0) = pwh0;
            *reinterpret_cast<uint4*>(sm + GOFF_WHI(nxt) + wdst1) = pwh1;
            const float4 uu = *reinterpret_cast<const float4*>(u_sh + jn + chunk4);
            const float4 vv = *reinterpret_cast<const float4*>(v_sh + jn + chunk4);
            #pragma unroll
            for (int i = 0; i < 4; i++) {
                const int row = r16 + 16 * i;
                const int4 av = adjr[i];
                float4 p;
                p.x = fmaxf(Ar[i] * uu.x, Br[i] * vv.x) * __int_as_float(av.x << 30);
                p.y = fmaxf(Ar[i] * uu.y, Br[i] * vv.y) * __int_as_float(av.y << 30);
                p.z = fmaxf(Ar[i] * uu.z, Br[i] * vv.z) * __int_as_float(av.z << 30);
                p.w = fmaxf(Ar[i] * uu.w, Br[i] * vv.w) * __int_as_float(av.w << 30);
                zacc[i] += (p.x + p.y) + (p.z + p.w);
                const uint32_t h0 = pkhf2(p.x, p.y);
                const uint32_t h1 = pkhf2(p.z, p.w);
                const float2 f0 = uph2(h0), f1 = uph2(h1);
                const uint32_t l0 = pkhf2(p.x - f0.x, p.y - f0.y);
                const uint32_t l1 = pkhf2(p.z - f1.x, p.w - f1.y);
                const uint32_t swo = (uint32_t)(row * 128 + (((chunk >> 1) ^ (row & 7)) << 4) +
                                                ((chunk & 1) << 3));
                *reinterpret_cast<uint2*>(sm + GOFF_PHI(nxt) + swo) = make_uint2(h0, h1);
                *reinterpret_cast<uint2*>(sm + GOFF_PLO(nxt) + swo) = make_uint2(l0, l1);
            }
        }
        __syncthreads();
    }

    // ---- Z reduction (alias P_HI(0)) ----
    float* zp = reinterpret_cast<float*>(sm + GOFF_PHI(0));
    #pragma unroll
    for (int i = 0; i < 4; i++) zp[i * 256 + tid] = zacc[i];
    __syncthreads();
    if (tid < 64) {
        const float* src = zp + (tid >> 4) * 256 + (tid & 15) * 16;
        float z = 0.f;
        #pragma unroll
        for (int t = 0; t < 16; t++) z += src[t];
        zf[tid] = z;   // row = (tid & 15) + 16*(tid >> 4) = tid
    }
    __syncthreads();

    // ---- normalize + store ----
    const int r0 = mq * 16 + (lid >> 2), r1 = r0 + 8;
    const float inv0 = 1.f / zf[r0];
    const float inv1 = 1.f / zf[r1];
    float* o0 = out + (size_t)(gi0 + r0) * DOUT + nh * 32 + (lid & 3) * 2;
    float* o1 = out + (size_t)(gi0 + r1) * DOUT + nh * 32 + (lid & 3) * 2;
    #pragma unroll
    for (int nt = 0; nt < 4; nt++) {
        *reinterpret_cast<float2*>(o0 + nt * 8) = make_float2(acc[nt][0] * inv0, acc[nt][1] * inv0);
        *reinterpret_cast<float2*>(o1 + nt * 8) = make_float2(acc[nt][2] * inv1, acc[nt][3] * inv1);
    }
}

// ============================================================
extern "C" void kernel_launch(void* const* d_in, const int* in_sizes, int n_in,
                              void* d_out, int out_size) {
    const float* h   = (const float*)d_in[0];
    const int*   adj = (const int*)d_in[1];
    const float* W   = (const float*)d_in[2];
    const float* a   = (const float*)d_in[3];
    float* out = (float*)d_out;

    cudaFuncSetAttribute(gat_main, cudaFuncAttributeMaxDynamicSharedMemorySize, GAT_SMEM);
    cudaFuncSetAttribute(wh_kernel, cudaFuncAttributeMaxDynamicSharedMemorySize, WH_SMEM);

    wh_kernel<<<(BATCH * NN) / 128, 256, WH_SMEM>>>(h, W, a);
    s2max_kernel<<<BATCH, 256>>>();
    gat_main<<<(BATCH * NN) / 64, 256, GAT_SMEM>>>(adj, out);
}

// round 7
// speedup vs baseline: 4.3202x; 1.1814x over previous
#include <cuda_runtime.h>
#include <cuda_bf16.h>
#include <cuda_fp16.h>
#include <cstdint>

#define BATCH 8
#define NN    2048
#define KDIM  256
#define DOUT  64
#define ALPHA 0.2f

// ---------------- scratch ----------------
__device__ __half g_WhT[BATCH * DOUT * NN];   // [b][d][j] fp16, 2MB
__device__ float g_s1[BATCH * NN];
__device__ float g_s2[BATCH * NN];
__device__ unsigned int g_s2max_u[BATCH];     // order-preserving float keys (0 == -NaN)

// ---------------- helpers ----------------
__device__ __forceinline__ uint32_t smem_u32(const void* p) {
    uint32_t a;
    asm("{ .reg .u64 t; cvta.to.shared.u64 t, %1; cvt.u32.u64 %0, t; }" : "=r"(a) : "l"(p));
    return a;
}
__device__ __forceinline__ void ldsm4(uint32_t (&r)[4], uint32_t addr) {
    asm volatile("ldmatrix.sync.aligned.m8n8.x4.shared.b16 {%0,%1,%2,%3}, [%4];"
                 : "=r"(r[0]), "=r"(r[1]), "=r"(r[2]), "=r"(r[3]) : "r"(addr));
}
__device__ __forceinline__ void mma_bf16(float (&d)[4], const uint32_t (&a)[4],
                                         uint32_t b0, uint32_t b1) {
    asm volatile("mma.sync.aligned.m16n8k16.row.col.f32.bf16.bf16.f32 "
                 "{%0,%1,%2,%3}, {%4,%5,%6,%7}, {%8,%9}, {%0,%1,%2,%3};"
                 : "+f"(d[0]), "+f"(d[1]), "+f"(d[2]), "+f"(d[3])
                 : "r"(a[0]), "r"(a[1]), "r"(a[2]), "r"(a[3]), "r"(b0), "r"(b1));
}
__device__ __forceinline__ void mma_f16(float (&d)[4], const uint32_t (&a)[4],
                                        uint32_t b0, uint32_t b1) {
    asm volatile("mma.sync.aligned.m16n8k16.row.col.f32.f16.f16.f32 "
                 "{%0,%1,%2,%3}, {%4,%5,%6,%7}, {%8,%9}, {%0,%1,%2,%3};"
                 : "+f"(d[0]), "+f"(d[1]), "+f"(d[2]), "+f"(d[3])
                 : "r"(a[0]), "r"(a[1]), "r"(a[2]), "r"(a[3]), "r"(b0), "r"(b1));
}
__device__ __forceinline__ uint32_t pkbf2(float x, float y) {
    __nv_bfloat162 t = __floats2bfloat162_rn(x, y);
    return *reinterpret_cast<uint32_t*>(&t);
}
__device__ __forceinline__ uint32_t hibits2(float x, float y) {
    return __byte_perm(__float_as_uint(x), __float_as_uint(y), 0x7632);
}
__device__ __forceinline__ float resid(float x) {
    return x - __uint_as_float(__float_as_uint(x) & 0xFFFF0000u);
}
__device__ __forceinline__ uint32_t pkhf2(float x, float y) {
    __half2 t = __floats2half2_rn(x, y);
    return *reinterpret_cast<uint32_t*>(&t);
}
__device__ __forceinline__ uint32_t fkey(float f) {
    const uint32_t b = __float_as_uint(f);
    return b ^ ((uint32_t)((int)b >> 31) | 0x80000000u);
}
__device__ __forceinline__ float funkey(uint32_t k) {
    const uint32_t b = (k & 0x80000000u) ? (k ^ 0x80000000u) : ~k;
    return __uint_as_float(b);
}

// ============================================================
// Kernel A (HMMA): Wh = h @ W. 256 CTAs x 64 rows, 8 warps,
// warp = 16 rows x 32 dims, 2 CTAs/SM. Emits s1, s2 (+atomicMax key),
// WhT fp16. 3-split bf16 MMA for accuracy.
// ============================================================
#define WOFF_HH 0
#define WOFF_HL 8192
#define WOFF_WH 16384
#define WOFF_WL 24576
#define WOFF_TR 0
#define WOFF_PS 32768
#define WH_SMEM 33792

__global__ __launch_bounds__(256, 2) void wh_kernel(const float* __restrict__ h,
                                                    const float* __restrict__ W,
                                                    const float* __restrict__ a) {
    extern __shared__ char sw[];
    const uint32_t smb = smem_u32(sw);
    const int tid = threadIdx.x;
    const int wid = tid >> 5, lid = tid & 31;
    const int gi0 = blockIdx.x * 64;
    const int b = gi0 >> 11;
    const int rowb = gi0 & 2047;

    float acc[4][4];
    #pragma unroll
    for (int n = 0; n < 4; n++)
        #pragma unroll
        for (int k = 0; k < 4; k++) acc[n][k] = 0.f;

    const int mq = wid & 3, nh = wid >> 2;
    const int rr = lid & 7, q = lid >> 3, qh = q >> 1, ql = q & 1;
    const int rowA = mq * 16 + rr + (ql << 3);
    const uint32_t baseA = (uint32_t)(rowA * 128);
    const int xA = rowA & 7;
    const int rbB = nh * 32 + (qh << 3) + rr;

    const int hrow = tid >> 2, hq = tid & 3;
    const float* hsrc = h + (size_t)(gi0 + hrow) * KDIM + hq * 16;
    const int wdd = tid >> 2, wkg = tid & 3;

    for (int kt = 0; kt < 4; kt++) {
        __syncthreads();
        // ---- stage h chunk [64 rows][64 k] hi/lo ----
        #pragma unroll
        for (int g = 0; g < 2; g++) {
            const float4 f0 = *reinterpret_cast<const float4*>(hsrc + kt * 64 + g * 8);
            const float4 f1 = *reinterpret_cast<const float4*>(hsrc + kt * 64 + g * 8 + 4);
            uint4 hi4, lo4;
            hi4.x = hibits2(f0.x, f0.y); hi4.y = hibits2(f0.z, f0.w);
            hi4.z = hibits2(f1.x, f1.y); hi4.w = hibits2(f1.z, f1.w);
            lo4.x = pkbf2(resid(f0.x), resid(f0.y));
            lo4.y = pkbf2(resid(f0.z), resid(f0.w));
            lo4.z = pkbf2(resid(f1.x), resid(f1.y));
            lo4.w = pkbf2(resid(f1.z), resid(f1.w));
            const int gran = hq * 2 + g;
            const uint32_t addr = (uint32_t)(hrow * 128 + ((gran ^ (hrow & 7)) << 4));
            *reinterpret_cast<uint4*>(sw + WOFF_HH + addr) = hi4;
            *reinterpret_cast<uint4*>(sw + WOFF_HL + addr) = lo4;
        }
        // ---- stage W^T chunk [64 d][64 k] hi/lo ----
        {
            uint32_t hi[8], lo[8];
            #pragma unroll
            for (int t = 0; t < 8; t++) {
                const float x0 = W[(kt * 64 + wkg * 16 + 2 * t) * DOUT + wdd];
                const float x1 = W[(kt * 64 + wkg * 16 + 2 * t + 1) * DOUT + wdd];
                hi[t] = hibits2(x0, x1);
                lo[t] = pkbf2(resid(x0), resid(x1));
            }
            const uint32_t a0 = (uint32_t)(wdd * 128 + (((wkg * 2) ^ (wdd & 7)) << 4));
            const uint32_t a1 = (uint32_t)(wdd * 128 + (((wkg * 2 + 1) ^ (wdd & 7)) << 4));
            *reinterpret_cast<uint4*>(sw + WOFF_WH + a0) = make_uint4(hi[0], hi[1], hi[2], hi[3]);
            *reinterpret_cast<uint4*>(sw + WOFF_WH + a1) = make_uint4(hi[4], hi[5], hi[6], hi[7]);
            *reinterpret_cast<uint4*>(sw + WOFF_WL + a0) = make_uint4(lo[0], lo[1], lo[2], lo[3]);
            *reinterpret_cast<uint4*>(sw + WOFF_WL + a1) = make_uint4(lo[4], lo[5], lo[6], lo[7]);
        }
        __syncthreads();
        // ---- 3-split bf16 MMA ----
        #pragma unroll
        for (int t = 0; t < 4; t++) {
            uint32_t Ah[4], Al[4];
            const uint32_t ua = baseA + (uint32_t)(((2 * t + qh) ^ xA) << 4);
            ldsm4(Ah, smb + WOFF_HH + ua);
            ldsm4(Al, smb + WOFF_HL + ua);
            #pragma unroll
            for (int ntp = 0; ntp < 2; ntp++) {
                const int rowB = rbB + ntp * 16;
                const uint32_t ab = (uint32_t)(rowB * 128 + (((2 * t + ql) ^ (rowB & 7)) << 4));
                uint32_t Bh[4], Bl[4];
                ldsm4(Bh, smb + WOFF_WH + ab);
                ldsm4(Bl, smb + WOFF_WL + ab);
                mma_bf16(acc[2 * ntp],     Ah, Bh[0], Bh[1]);
                mma_bf16(acc[2 * ntp],     Ah, Bl[0], Bl[1]);
                mma_bf16(acc[2 * ntp],     Al, Bh[0], Bh[1]);
                mma_bf16(acc[2 * ntp + 1], Ah, Bh[2], Bh[3]);
                mma_bf16(acc[2 * ntp + 1], Ah, Bl[2], Bl[3]);
                mma_bf16(acc[2 * ntp + 1], Al, Bh[2], Bh[3]);
            }
        }
    }
    __syncthreads();

    // ---- epilogue: s1/s2 partials + fp16 WhT staging ----
    const int r0 = mq * 16 + (lid >> 2), r1 = r0 + 8;
    float s1r0 = 0.f, s2r0 = 0.f, s1r1 = 0.f, s2r1 = 0.f;
    __half* tr = reinterpret_cast<__half*>(sw + WOFF_TR);   // [64 d][64 r]
    float* ps1 = reinterpret_cast<float*>(sw + WOFF_PS);    // [2][64]
    float* ps2 = ps1 + 128;
    #pragma unroll
    for (int nt = 0; nt < 4; nt++) {
        const int d0 = nh * 32 + nt * 8 + (lid & 3) * 2;
        const float a10 = a[d0], a11 = a[d0 + 1];
        const float a20 = a[64 + d0], a21 = a[64 + d0 + 1];
        s1r0 = fmaf(acc[nt][0], a10, fmaf(acc[nt][1], a11, s1r0));
        s2r0 = fmaf(acc[nt][0], a20, fmaf(acc[nt][1], a21, s2r0));
        s1r1 = fmaf(acc[nt][2], a10, fmaf(acc[nt][3], a11, s1r1));
        s2r1 = fmaf(acc[nt][2], a20, fmaf(acc[nt][3], a21, s2r1));
        tr[(d0 + 0) * 64 + r0] = __float2half_rn(acc[nt][0]);
        tr[(d0 + 1) * 64 + r0] = __float2half_rn(acc[nt][1]);
        tr[(d0 + 0) * 64 + r1] = __float2half_rn(acc[nt][2]);
        tr[(d0 + 1) * 64 + r1] = __float2half_rn(acc[nt][3]);
    }
    #pragma unroll
    for (int off = 1; off <= 2; off <<= 1) {
        s1r0 += __shfl_xor_sync(0xffffffffu, s1r0, off);
        s2r0 += __shfl_xor_sync(0xffffffffu, s2r0, off);
        s1r1 += __shfl_xor_sync(0xffffffffu, s1r1, off);
        s2r1 += __shfl_xor_sync(0xffffffffu, s2r1, off);
    }
    if ((lid & 3) == 0) {
        ps1[nh * 64 + r0] = s1r0; ps2[nh * 64 + r0] = s2r0;
        ps1[nh * 64 + r1] = s1r1; ps2[nh * 64 + r1] = s2r1;
    }
    __syncthreads();

    if (tid < 64) {
        const float s1 = ps1[tid] + ps1[64 + tid];
        const float s2 = ps2[tid] + ps2[64 + tid];
        g_s1[gi0 + tid] = s1;
        g_s2[gi0 + tid] = s2;
        float m = s2;
        #pragma unroll
        for (int off = 16; off; off >>= 1) m = fmaxf(m, __shfl_down_sync(0xffffffffu, m, off));
        if ((tid & 31) == 0) atomicMax(&g_s2max_u[b], fkey(m));
    }

    // ---- write WhT (coalesced): 512 16B chunks = 64 d x 8 row-chunks ----
    #pragma unroll
    for (int c = 0; c < 2; c++) {
        const int idx = tid + 256 * c;
        const int d = idx >> 3;
        const int c8 = idx & 7;
        const uint4 val = *reinterpret_cast<const uint4*>(tr + d * 64 + c8 * 8);
        *reinterpret_cast<uint4*>(g_WhT + ((size_t)(b * DOUT + d)) * NN + rowb + c8 * 8) = val;
    }
}

// ============================================================
// Kernel B: fp16 HMMA GAT main, single-plane P. 256 CTAs x 64 rows,
// 8 warps (16 rows x 32 dims), 2 CTAs/SM, ping-pong pipeline.
// ============================================================
#define GOFF_PHI(s) ((s) * 8192)
#define GOFF_WHI(s) (16384 + (s) * 8192)
#define GOFF_U   32768
#define GOFF_V   40960
#define GOFF_AS  49152
#define GOFF_BS  49408
#define GOFF_ZF  49664
#define GAT_SMEM 49920

__global__ __launch_bounds__(256, 2) void gat_main(const int* __restrict__ adj,
                                                   float* __restrict__ out) {
    extern __shared__ char sm[];
    const uint32_t smb = smem_u32(sm);
    const int tid = threadIdx.x;
    const int wid = tid >> 5, lid = tid & 31;
    const int gi0 = blockIdx.x * 64;
    const int b = gi0 >> 11;

    float* u_sh = reinterpret_cast<float*>(sm + GOFF_U);
    float* v_sh = reinterpret_cast<float*>(sm + GOFF_V);
    float* As = reinterpret_cast<float*>(sm + GOFF_AS);
    float* Bs = reinterpret_cast<float*>(sm + GOFF_BS);
    float* zf = reinterpret_cast<float*>(sm + GOFF_ZF);

    // ---- prologue ----
    const float s2m = funkey(g_s2max_u[b]);
    for (int j = tid; j < NN; j += 256) {
        const float s2 = g_s2[b * NN + j];
        u_sh[j] = __expf(s2);
        v_sh[j] = __expf(ALPHA * s2);
    }
    if (tid < 64) {
        const float s1 = g_s1[gi0 + tid];
        const float t = s1 + s2m;
        const float m = (t > 0.f) ? t : ALPHA * t;
        As[tid] = 0.5f * __expf(s1 - m);
        Bs[tid] = 0.5f * __expf(ALPHA * s1 - m);
    }
    __syncthreads();

    // ---- geometry ----
    const int r16 = tid >> 4;
    const int chunk = tid & 15;
    const int chunk4 = chunk * 4;

    float Ar[4], Br[4];
    #pragma unroll
    for (int i = 0; i < 4; i++) { Ar[i] = As[r16 + 16 * i]; Br[i] = Bs[r16 + 16 * i]; }

    float acc[4][4];
    #pragma unroll
    for (int n = 0; n < 4; n++)
        #pragma unroll
        for (int k = 0; k < 4; k++) acc[n][k] = 0.f;
    float zacc[4] = {0.f, 0.f, 0.f, 0.f};

    const int mq = wid & 3, nh = wid >> 2;
    const int rr = lid & 7, q = lid >> 3, qh = q >> 1, ql = q & 1;
    const int rowA = mq * 16 + rr + (ql << 3);
    const uint32_t baseA = (uint32_t)(rowA * 128);
    const int xA = rowA & 7;
    const int rbB = nh * 32 + (qh << 3) + rr;

    const int wdrow = tid >> 3, wun = tid & 7;
    const uint32_t wdst0 = (uint32_t)(wdrow * 128 + ((wun ^ (wdrow & 7)) << 4));
    const uint32_t wdst1 = (uint32_t)((wdrow + 32) * 128 + ((wun ^ ((wdrow + 32) & 7)) << 4));
    const __half* wsrc = g_WhT + ((size_t)(b * DOUT + wdrow)) * NN + wun * 8;
    const int* asrc = adj + (size_t)(gi0 + r16) * NN + chunk4;

    // ---- prefetch ----
    int4 adjr[4];
    uint4 pwh0, pwh1;
    #pragma unroll
    for (int i = 0; i < 4; i++)
        adjr[i] = *reinterpret_cast<const int4*>(asrc + (size_t)(16 * i) * NN);
    pwh0 = *reinterpret_cast<const uint4*>(wsrc);
    pwh1 = *reinterpret_cast<const uint4*>(wsrc + (size_t)32 * NN);

    // build stage 0
    {
        *reinterpret_cast<uint4*>(sm + GOFF_WHI(0) + wdst0) = pwh0;
        *reinterpret_cast<uint4*>(sm + GOFF_WHI(0) + wdst1) = pwh1;
        const float4 uu = *reinterpret_cast<const float4*>(u_sh + chunk4);
        const float4 vv = *reinterpret_cast<const float4*>(v_sh + chunk4);
        #pragma unroll
        for (int i = 0; i < 4; i++) {
            const int row = r16 + 16 * i;
            const int4 av = adjr[i];
            float4 p;
            p.x = fmaxf(Ar[i] * uu.x, Br[i] * vv.x) * __int_as_float(av.x << 30);
            p.y = fmaxf(Ar[i] * uu.y, Br[i] * vv.y) * __int_as_float(av.y << 30);
            p.z = fmaxf(Ar[i] * uu.z, Br[i] * vv.z) * __int_as_float(av.z << 30);
            p.w = fmaxf(Ar[i] * uu.w, Br[i] * vv.w) * __int_as_float(av.w << 30);
            zacc[i] += (p.x + p.y) + (p.z + p.w);
            const uint32_t h0 = pkhf2(p.x, p.y);
            const uint32_t h1 = pkhf2(p.z, p.w);
            const uint32_t swo = (uint32_t)(row * 128 + (((chunk >> 1) ^ (row & 7)) << 4) +
                                            ((chunk & 1) << 3));
            *reinterpret_cast<uint2*>(sm + GOFF_PHI(0) + swo) = make_uint2(h0, h1);
        }
    }
    __syncthreads();

    for (int jt = 0; jt < 32; jt++) {
        const int cur = jt & 1;
        const bool more = (jt < 31);
        const int jn = (jt + 1) * 64;

        if (more) {
            #pragma unroll
            for (int i = 0; i < 4; i++)
                adjr[i] = *reinterpret_cast<const int4*>(asrc + (size_t)(16 * i) * NN + jn);
            pwh0 = *reinterpret_cast<const uint4*>(wsrc + jn);
            pwh1 = *reinterpret_cast<const uint4*>(wsrc + (size_t)32 * NN + jn);
        }

        // ---- MMA on current stage: single-plane P ----
        {
            const uint32_t oPhi = GOFF_PHI(cur), oWhi = GOFF_WHI(cur);
            #pragma unroll
            for (int t = 0; t < 4; t++) {
                uint32_t Ah[4];
                const uint32_t ua = baseA + (uint32_t)(((2 * t + qh) ^ xA) << 4);
                ldsm4(Ah, smb + oPhi + ua);
                #pragma unroll
                for (int ntp = 0; ntp < 2; ntp++) {
                    const int rowB = rbB + ntp * 16;
                    const uint32_t ab = (uint32_t)(rowB * 128 +
                                                   (((2 * t + ql) ^ (rowB & 7)) << 4));
                    uint32_t Bh[4];
                    ldsm4(Bh, smb + oWhi + ab);
                    mma_f16(acc[2 * ntp],     Ah, Bh[0], Bh[1]);
                    mma_f16(acc[2 * ntp + 1], Ah, Bh[2], Bh[3]);
                }
            }
        }

        // ---- build next stage ----
        if (more) {
            const int nxt = cur ^ 1;
            *reinterpret_cast<uint4*>(sm + GOFF_WHI(nxt) + wdst0) = pwh0;
            *reinterpret_cast<uint4*>(sm + GOFF_WHI(nxt) + wdst1) = pwh1;
            const float4 uu = *reinterpret_cast<const float4*>(u_sh + jn + chunk4);
            const float4 vv = *reinterpret_cast<const float4*>(v_sh + jn + chunk4);
            #pragma unroll
            for (int i = 0; i < 4; i++) {
                const int row = r16 + 16 * i;
                const int4 av = adjr[i];
                float4 p;
                p.x = fmaxf(Ar[i] * uu.x, Br[i] * vv.x) * __int_as_float(av.x << 30);
                p.y = fmaxf(Ar[i] * uu.y, Br[i] * vv.y) * __int_as_float(av.y << 30);
                p.z = fmaxf(Ar[i] * uu.z, Br[i] * vv.z) * __int_as_float(av.z << 30);
                p.w = fmaxf(Ar[i] * uu.w, Br[i] * vv.w) * __int_as_float(av.w << 30);
                zacc[i] += (p.x + p.y) + (p.z + p.w);
                const uint32_t h0 = pkhf2(p.x, p.y);
                const uint32_t h1 = pkhf2(p.z, p.w);
                const uint32_t swo = (uint32_t)(row * 128 + (((chunk >> 1) ^ (row & 7)) << 4) +
                                                ((chunk & 1) << 3));
                *reinterpret_cast<uint2*>(sm + GOFF_PHI(nxt) + swo) = make_uint2(h0, h1);
            }
        }
        __syncthreads();
    }

    // ---- Z reduction (alias P_HI(0)) ----
    float* zp = reinterpret_cast<float*>(sm + GOFF_PHI(0));
    #pragma unroll
    for (int i = 0; i < 4; i++) zp[i * 256 + tid] = zacc[i];
    __syncthreads();
    if (tid < 64) {
        const float* src = zp + (tid >> 4) * 256 + (tid & 15) * 16;
        float z = 0.f;
        #pragma unroll
        for (int t = 0; t < 16; t++) z += src[t];
        zf[tid] = z;
    }
    __syncthreads();

    // ---- normalize + store ----
    const int r0 = mq * 16 + (lid >> 2), r1 = r0 + 8;
    const float inv0 = 1.f / zf[r0];
    const float inv1 = 1.f / zf[r1];
    float* o0 = out + (size_t)(gi0 + r0) * DOUT + nh * 32 + (lid & 3) * 2;
    float* o1 = out + (size_t)(gi0 + r1) * DOUT + nh * 32 + (lid & 3) * 2;
    #pragma unroll
    for (int nt = 0; nt < 4; nt++) {
        *reinterpret_cast<float2*>(o0 + nt * 8) = make_float2(acc[nt][0] * inv0, acc[nt][1] * inv0);
        *reinterpret_cast<float2*>(o1 + nt * 8) = make_float2(acc[nt][2] * inv1, acc[nt][3] * inv1);
    }
}

// ============================================================
extern "C" void kernel_launch(void* const* d_in, const int* in_sizes, int n_in,
                              void* d_out, int out_size) {
    const float* h   = (const float*)d_in[0];
    const int*   adj = (const int*)d_in[1];
    const float* W   = (const float*)d_in[2];
    const float* a   = (const float*)d_in[3];
    float* out = (float*)d_out;

    cudaFuncSetAttribute(gat_main, cudaFuncAttributeMaxDynamicSharedMemorySize, GAT_SMEM);
    cudaFuncSetAttribute(wh_kernel, cudaFuncAttributeMaxDynamicSharedMemorySize, WH_SMEM);

    wh_kernel<<<(BATCH * NN) / 64, 256, WH_SMEM>>>(h, W, a);
    gat_main<<<(BATCH * NN) / 64, 256, GAT_SMEM>>>(adj, out);
}